// round 8
// baseline (speedup 1.0000x reference)
#include <cuda_runtime.h>
#include <cuda_bf16.h>
#include <math.h>
#include <stdint.h>

// ---------------- problem constants ----------------
constexpr int NRES  = 768;
constexpr int NH    = 12;
constexpr long long NP = (long long)NRES * NRES;   // 589824
constexpr int DQKV  = 1152;
constexpr int DSC   = 384;
constexpr int DOUT  = 2112;
constexpr int QS_OFF = 0, KS_OFF = 192, VS_OFF = 384, QP_OFF = 576, KP_OFF = 720, VP_OFF = 864;
constexpr float SSC  = 0.14433756729740643f;
constexpr float PSC  = 0.13608276348795434f;
constexpr float PBSC = 0.5773502691896258f;

// ---------------- scratch ----------------
__device__ float g_qkv[NRES * DQKV];
__device__ float g_qp[NRES * 144];
__device__ float g_kp[NRES * 144];
__device__ float g_vp[NRES * 288];
__device__ float g_qpack[NRES * 336];      // [i][h*28+d]
__device__ float g_kpackT[336 * NRES];     // [h*28+d][j]
__device__ float g_edge[(size_t)NP * 36];  // [i][c][j] softmaxed; c<12 == attn head c
__device__ float g_feats[NRES * DOUT];
__device__ float g_respts[NRES * 288];

__device__ __forceinline__ float gelu_exact(float x) {
    return 0.5f * x * (1.0f + erff(x * 0.70710678118654752f));
}

// ---------------- mma helpers ----------------
__device__ __forceinline__ uint32_t s2u(const void* p) {
    uint32_t a;
    asm("{.reg .u64 t; cvta.to.shared.u64 t, %1; cvt.u32.u64 %0, t;}" : "=r"(a) : "l"(p));
    return a;
}
__device__ __forceinline__ void ldm4(uint32_t r[4], uint32_t a) {
    asm volatile("ldmatrix.sync.aligned.m8n8.x4.shared.b16 {%0,%1,%2,%3},[%4];"
                 : "=r"(r[0]), "=r"(r[1]), "=r"(r[2]), "=r"(r[3]) : "r"(a));
}
__device__ __forceinline__ void ldm4t(uint32_t r[4], uint32_t a) {
    asm volatile("ldmatrix.sync.aligned.m8n8.x4.trans.shared.b16 {%0,%1,%2,%3},[%4];"
                 : "=r"(r[0]), "=r"(r[1]), "=r"(r[2]), "=r"(r[3]) : "r"(a));
}
__device__ __forceinline__ void mma_bf16(float c[4], const uint32_t a[4], uint32_t b0, uint32_t b1) {
    asm volatile(
        "mma.sync.aligned.m16n8k16.row.col.f32.bf16.bf16.f32 "
        "{%0,%1,%2,%3},{%4,%5,%6,%7},{%8,%9},{%0,%1,%2,%3};"
        : "+f"(c[0]), "+f"(c[1]), "+f"(c[2]), "+f"(c[3])
        : "r"(a[0]), "r"(a[1]), "r"(a[2]), "r"(a[3]), "r"(b0), "r"(b1));
}
__device__ __forceinline__ void split1(float v, __nv_bfloat16& h, __nv_bfloat16& l) {
    h = __float2bfloat16_rn(v);
    l = __float2bfloat16_rn(v - __bfloat162float(h));
}
__device__ __forceinline__ void split2(float x, float y, uint32_t& hi, uint32_t& lo) {
    __nv_bfloat16 hx = __float2bfloat16_rn(x), hy = __float2bfloat16_rn(y);
    float rx = x - __bfloat162float(hx), ry = y - __bfloat162float(hy);
    __nv_bfloat162 th = __halves2bfloat162(hx, hy);
    __nv_bfloat162 tl = __floats2bfloat162_rn(rx, ry);
    hi = *reinterpret_cast<uint32_t*>(&th);
    lo = *reinterpret_cast<uint32_t*>(&tl);
}

// ---------------- generic 3-pass bf16 tensor-core GEMM (qkv) ----------------
constexpr int GAP = 24;
constexpr int GBP = 136;
__global__ __launch_bounds__(256) void gemm_mma3(
    const float* __restrict__ A, const float* __restrict__ B, float* __restrict__ C,
    int M, int N, int K, const float* __restrict__ bias)
{
    __shared__ __nv_bfloat16 Ah[128 * GAP], Al[128 * GAP];
    __shared__ __nv_bfloat16 Bh[16 * GBP],  Bl[16 * GBP];
    uint32_t sb_ah = s2u(Ah), sb_al = s2u(Al), sb_bh = s2u(Bh), sb_bl = s2u(Bl);
    int tid = threadIdx.x, lane = tid & 31, w = tid >> 5;
    int bm = blockIdx.y * 128, bn = blockIdx.x * 128;
    int r0 = w * 16;
    uint32_t aAoff = r0 * (GAP * 2) + (lane & 15) * (GAP * 2) + (lane >> 4) * 16;
    int brow = (lane & 7) + ((lane >> 3) & 1) * 8, bc8 = (lane >> 4) * 8;
    uint32_t aBoff = brow * (GBP * 2) + bc8 * 2;

    float acc[16][4] = {};
    for (int k0 = 0; k0 < K; k0 += 16) {
#pragma unroll
        for (int rep = 0; rep < 2; rep++) {
            int idx = tid + rep * 256;
            int row = idx >> 2, c4 = (idx & 3) * 4;
            float4 v = *(const float4*)&A[(size_t)(bm + row) * K + k0 + c4];
            split1(v.x, Ah[row * GAP + c4],     Al[row * GAP + c4]);
            split1(v.y, Ah[row * GAP + c4 + 1], Al[row * GAP + c4 + 1]);
            split1(v.z, Ah[row * GAP + c4 + 2], Al[row * GAP + c4 + 2]);
            split1(v.w, Ah[row * GAP + c4 + 3], Al[row * GAP + c4 + 3]);
            int browi = idx >> 5, bc4 = (idx & 31) * 4;
            float4 u = *(const float4*)&B[(size_t)(k0 + browi) * N + bn + bc4];
            split1(u.x, Bh[browi * GBP + bc4],     Bl[browi * GBP + bc4]);
            split1(u.y, Bh[browi * GBP + bc4 + 1], Bl[browi * GBP + bc4 + 1]);
            split1(u.z, Bh[browi * GBP + bc4 + 2], Bl[browi * GBP + bc4 + 2]);
            split1(u.w, Bh[browi * GBP + bc4 + 3], Bl[browi * GBP + bc4 + 3]);
        }
        __syncthreads();
        uint32_t ah[4], al[4];
        ldm4(ah, sb_ah + aAoff);
        ldm4(al, sb_al + aAoff);
#pragma unroll
        for (int n = 0; n < 8; n++) {
            uint32_t bh[4], bl[4];
            ldm4t(bh, sb_bh + aBoff + n * 32);
            ldm4t(bl, sb_bl + aBoff + n * 32);
            mma_bf16(acc[2 * n], ah, bh[0], bh[1]);
            mma_bf16(acc[2 * n], ah, bl[0], bl[1]);
            mma_bf16(acc[2 * n], al, bh[0], bh[1]);
            mma_bf16(acc[2 * n + 1], ah, bh[2], bh[3]);
            mma_bf16(acc[2 * n + 1], ah, bl[2], bl[3]);
            mma_bf16(acc[2 * n + 1], al, bh[2], bh[3]);
        }
        __syncthreads();
    }
    int rlo = bm + r0 + (lane >> 2);
#pragma unroll
    for (int n = 0; n < 16; n++) {
        int c = bn + n * 8 + (lane & 3) * 2;
        float b0 = bias ? bias[c] : 0.f, b1v = bias ? bias[c + 1] : 0.f;
        *(float2*)&C[(size_t)rlo * N + c] = make_float2(acc[n][0] + b0, acc[n][1] + b1v);
        *(float2*)&C[(size_t)(rlo + 8) * N + c] = make_float2(acc[n][2] + b0, acc[n][3] + b1v);
    }
}

// ---------------- split-K GEMM for scalar_out (atomicAdd epilogue) ----------------
__global__ __launch_bounds__(256) void gemm_mma3_sk(
    const float* __restrict__ A, const float* __restrict__ B, float* __restrict__ C,
    int M, int N, int K, int kchunk)
{
    __shared__ __nv_bfloat16 Ah[128 * GAP], Al[128 * GAP];
    __shared__ __nv_bfloat16 Bh[16 * GBP],  Bl[16 * GBP];
    uint32_t sb_ah = s2u(Ah), sb_al = s2u(Al), sb_bh = s2u(Bh), sb_bl = s2u(Bl);
    int tid = threadIdx.x, lane = tid & 31, w = tid >> 5;
    int bm = blockIdx.y * 128, bn = blockIdx.x * 128;
    int kbeg = blockIdx.z * kchunk, kend = kbeg + kchunk;
    int r0 = w * 16;
    uint32_t aAoff = r0 * (GAP * 2) + (lane & 15) * (GAP * 2) + (lane >> 4) * 16;
    int brow = (lane & 7) + ((lane >> 3) & 1) * 8, bc8 = (lane >> 4) * 8;
    uint32_t aBoff = brow * (GBP * 2) + bc8 * 2;

    float acc[16][4] = {};
    for (int k0 = kbeg; k0 < kend; k0 += 16) {
#pragma unroll
        for (int rep = 0; rep < 2; rep++) {
            int idx = tid + rep * 256;
            int row = idx >> 2, c4 = (idx & 3) * 4;
            float4 v = *(const float4*)&A[(size_t)(bm + row) * K + k0 + c4];
            split1(v.x, Ah[row * GAP + c4],     Al[row * GAP + c4]);
            split1(v.y, Ah[row * GAP + c4 + 1], Al[row * GAP + c4 + 1]);
            split1(v.z, Ah[row * GAP + c4 + 2], Al[row * GAP + c4 + 2]);
            split1(v.w, Ah[row * GAP + c4 + 3], Al[row * GAP + c4 + 3]);
            int browi = idx >> 5, bc4 = (idx & 31) * 4;
            float4 u = *(const float4*)&B[(size_t)(k0 + browi) * N + bn + bc4];
            split1(u.x, Bh[browi * GBP + bc4],     Bl[browi * GBP + bc4]);
            split1(u.y, Bh[browi * GBP + bc4 + 1], Bl[browi * GBP + bc4 + 1]);
            split1(u.z, Bh[browi * GBP + bc4 + 2], Bl[browi * GBP + bc4 + 2]);
            split1(u.w, Bh[browi * GBP + bc4 + 3], Bl[browi * GBP + bc4 + 3]);
        }
        __syncthreads();
        uint32_t ah[4], al[4];
        ldm4(ah, sb_ah + aAoff);
        ldm4(al, sb_al + aAoff);
#pragma unroll
        for (int n = 0; n < 8; n++) {
            uint32_t bh[4], bl[4];
            ldm4t(bh, sb_bh + aBoff + n * 32);
            ldm4t(bl, sb_bl + aBoff + n * 32);
            mma_bf16(acc[2 * n], ah, bh[0], bh[1]);
            mma_bf16(acc[2 * n], ah, bl[0], bl[1]);
            mma_bf16(acc[2 * n], al, bh[0], bh[1]);
            mma_bf16(acc[2 * n + 1], ah, bh[2], bh[3]);
            mma_bf16(acc[2 * n + 1], ah, bl[2], bl[3]);
            mma_bf16(acc[2 * n + 1], al, bh[2], bh[3]);
        }
        __syncthreads();
    }
    int rlo = bm + r0 + (lane >> 2);
#pragma unroll
    for (int n = 0; n < 16; n++) {
        int c = bn + n * 8 + (lane & 3) * 2;
        atomicAdd(&C[(size_t)rlo * N + c], acc[n][0]);
        atomicAdd(&C[(size_t)rlo * N + c + 1], acc[n][1]);
        atomicAdd(&C[(size_t)(rlo + 8) * N + c], acc[n][2]);
        atomicAdd(&C[(size_t)(rlo + 8) * N + c + 1], acc[n][3]);
    }
}

__global__ void k_zero(float* __restrict__ out, const float* __restrict__ bout) {
    int idx = blockIdx.x * 256 + threadIdx.x;
    if (idx < NRES * DSC) out[idx] = bout[idx % DSC];
}

// ---------------- points to global frame ----------------
__global__ void k_points(const float* __restrict__ rot, const float* __restrict__ trans) {
    int i = blockIdx.x;
    int t = threadIdx.x;
    const float* q = g_qkv + (size_t)i * DQKV;
    float p0, p1, p2;
    float* dst;
    if (t < 48) {
        int c0 = QP_OFF + t * 3;
        p0 = q[c0]; p1 = q[c0 + 1]; p2 = q[c0 + 2];
        dst = g_qp + i * 144 + t * 3;
    } else if (t < 96) {
        int u = t - 48, c0 = KP_OFF + u * 3;
        p0 = q[c0]; p1 = q[c0 + 1]; p2 = q[c0 + 2];
        dst = g_kp + i * 144 + u * 3;
    } else {
        int u = t - 96, c0 = VP_OFF + u * 3;
        p0 = q[c0]; p1 = q[c0 + 1]; p2 = q[c0 + 2];
        dst = g_vp + i * 288 + u * 3;
    }
    const float* R = rot + i * 9;
    const float* tr = trans + i * 3;
#pragma unroll
    for (int x = 0; x < 3; x++)
        dst[x] = R[x * 3 + 0] * p0 + R[x * 3 + 1] * p1 + R[x * 3 + 2] * p2 + tr[x];
}

// ---------------- pack q (row-major) and k (transposed) ----------------
__global__ void k_pack() {
    int i = blockIdx.x;
    for (int idx = threadIdx.x; idx < 336; idx += 256) {
        int h = idx / 28, d = idx - h * 28;
        float qv, kv;
        if (d < 16) {
            qv = g_qkv[(size_t)i * DQKV + QS_OFF + h * 16 + d];
            kv = g_qkv[(size_t)i * DQKV + KS_OFF + h * 16 + d];
        } else {
            qv = g_qp[i * 144 + h * 12 + (d - 16)];
            kv = g_kp[i * 144 + h * 12 + (d - 16)];
        }
        g_qpack[i * 336 + idx] = qv;
        g_kpackT[(size_t)idx * NRES + i] = kv;
    }
}

// ================= fused: pair-bias + qk logits + softmax + res_pair =================
// 512 threads (16 warps), ~217 KB smem, 1 CTA/SM
constexpr int LP = 776;
constexpr int F_LOG = 0;                       // [36][LP]
constexpr int F_W   = F_LOG + 36 * LP;         // 1536
constexpr int F_Q   = F_W + 1536;              // 352
constexpr int F_SPH = F_Q + 352;               // 16
constexpr int F_RED = F_SPH + 16;              // 16*1536 (also pb scratch, pitch 769)
constexpr int F_TOT = F_RED + 16 * 1536;
constexpr int FUSED_SMEM = F_TOT * 4;

__global__ __launch_bounds__(512, 1) void k_fused(
    const float* __restrict__ pair, const float* __restrict__ Wpb, const float* __restrict__ pw)
{
    extern __shared__ float sh[];
    float* sLog = sh + F_LOG;
    float* sW   = sh + F_W;
    float* sQ   = sh + F_Q;
    float* sSph = sh + F_SPH;
    float* sRed = sh + F_RED;
    int i = blockIdx.x, tid = threadIdx.x;
    int w = tid >> 5, lane = tid & 31;

    for (int idx = tid; idx < 1536; idx += 512) sW[idx] = Wpb[idx];
    for (int idx = tid; idx < 336; idx += 512) sQ[idx] = g_qpack[i * 336 + idx];
    if (tid < 12) sSph[tid] = log1pf(__expf(pw[tid]));
    __syncthreads();

    const float* prowbase = pair + (size_t)i * NRES * 128;

    // --- pass A1: pair-bias, warp-per-j (coalesced pair read), pb -> sRed[h*769 + j] ---
    for (int j = w; j < NRES; j += 16) {
        float4 v = *(const float4*)(prowbase + (size_t)j * 128 + lane * 4);
        int k0 = lane * 4;
        float keep = 0.f;
#pragma unroll
        for (int h = 0; h < 12; h++) {
            float s = v.x * sW[k0 * 12 + h] + v.y * sW[(k0 + 1) * 12 + h]
                    + v.z * sW[(k0 + 2) * 12 + h] + v.w * sW[(k0 + 3) * 12 + h];
#pragma unroll
            for (int sft = 16; sft > 0; sft >>= 1)
                s += __shfl_xor_sync(0xffffffffu, s, sft);
            if (lane == h) keep = s;
        }
        if (lane < 12) sRed[lane * 769 + j] = keep;
    }
    __syncthreads();

    // --- pass A2: qk logits (coalesced via kpackT) + combine with pb ---
    for (int j = tid; j < NRES; j += 512) {
#pragma unroll
        for (int h = 0; h < 12; h++) {
            const float* qh = sQ + h * 28;
            const float* kb = g_kpackT + (size_t)(h * 28) * NRES + j;
            float sl = 0.f, pl = 0.f;
#pragma unroll
            for (int d = 0; d < 16; d++) sl += qh[d] * kb[(size_t)d * NRES];
#pragma unroll
            for (int d = 16; d < 28; d++) pl += qh[d] * kb[(size_t)d * NRES];
            float plv = pl * sSph[h];
            float pb = sRed[h * 769 + j];
            sLog[h * LP + j]        = SSC * sl + PSC * plv + PBSC * pb;
            sLog[(12 + h) * LP + j] = plv;
            sLog[(24 + h) * LP + j] = sl;
        }
    }
    __syncthreads();

    // --- pass B: softmax per channel (warp per channel) ---
    {
        for (int c = w; c < 36; c += 16) {
            float* row = sLog + c * LP;
            float v[24];
            float m = -1e30f;
#pragma unroll
            for (int t = 0; t < 24; t++) { v[t] = row[lane + t * 32]; m = fmaxf(m, v[t]); }
#pragma unroll
            for (int s = 16; s > 0; s >>= 1) m = fmaxf(m, __shfl_xor_sync(0xffffffffu, m, s));
            float sum = 0.f;
#pragma unroll
            for (int t = 0; t < 24; t++) { v[t] = __expf(v[t] - m); sum += v[t]; }
#pragma unroll
            for (int s = 16; s > 0; s >>= 1) sum += __shfl_xor_sync(0xffffffffu, sum, s);
            float inv = 1.f / sum;
            float* dst = g_edge + ((size_t)i * 36 + c) * NRES;
#pragma unroll
            for (int t = 0; t < 24; t++) {
                float p = v[t] * inv;
                dst[lane + t * 32] = p;
                if (c < 12) row[lane + t * 32] = p;
            }
        }
    }
    __syncthreads();

    // --- pass D: res_pair; pair row should be L2-hot from pass A1 ---
    {
        float acc[12][4] = {};
        for (int j = w; j < NRES; j += 16) {
            float4 v = *(const float4*)(prowbase + (size_t)j * 128 + lane * 4);
#pragma unroll
            for (int h = 0; h < 12; h++) {
                float a = sLog[h * LP + j];
                acc[h][0] += a * v.x; acc[h][1] += a * v.y;
                acc[h][2] += a * v.z; acc[h][3] += a * v.w;
            }
        }
        __syncthreads();   // pb scratch region now dead; safe to overwrite sRed
#pragma unroll
        for (int h = 0; h < 12; h++) {
            float* base = sRed + w * 1536 + h * 128 + lane * 4;
            base[0] = acc[h][0]; base[1] = acc[h][1]; base[2] = acc[h][2]; base[3] = acc[h][3];
        }
        __syncthreads();
        for (int idx = tid; idx < 1536; idx += 512) {
            float s = 0.f;
#pragma unroll
            for (int g = 0; g < 16; g++) s += sRed[g * 1536 + idx];
            int h = idx >> 7, d = idx & 127;
            g_feats[(size_t)i * DOUT + 192 + h * 128 + d] = s;
        }
    }
}

// ---------------- res_scalar + res_pts ----------------
__global__ __launch_bounds__(256) void k_resv() {
    int h = blockIdx.y;
    int i0 = blockIdx.x * 64;
    __shared__ float a[64][65];
    __shared__ float v[64][40];
    int tid = threadIdx.x;
    int io = tid & 63, og = tid >> 6;
    float acc[10] = {};
    for (int j0 = 0; j0 < NRES; j0 += 64) {
        for (int idx = tid; idx < 4096; idx += 256) {
            int ii = idx >> 6, jj = idx & 63;
            a[ii][jj] = g_edge[((size_t)(i0 + ii) * 36 + h) * NRES + j0 + jj];
        }
        for (int idx = tid; idx < 64 * 40; idx += 256) {
            int jj = idx / 40, o = idx - jj * 40;
            float val;
            if (o < 16) val = g_qkv[(size_t)(j0 + jj) * DQKV + VS_OFF + h * 16 + o];
            else        val = g_vp[(size_t)(j0 + jj) * 288 + h * 24 + (o - 16)];
            v[jj][o] = val;
        }
        __syncthreads();
#pragma unroll 4
        for (int jj = 0; jj < 64; jj++) {
            float av = a[io][jj];
#pragma unroll
            for (int q = 0; q < 10; q++) acc[q] += av * v[jj][og * 10 + q];
        }
        __syncthreads();
    }
#pragma unroll
    for (int q = 0; q < 10; q++) {
        int o = og * 10 + q;
        if (o < 16) g_feats[(size_t)(i0 + io) * DOUT + h * 16 + o] = acc[q];
        else        g_respts[(size_t)(i0 + io) * 288 + h * 24 + (o - 16)] = acc[q];
    }
}

// ---------------- inverse rigid + norms ----------------
__global__ void k_local(const float* __restrict__ rot, const float* __restrict__ trans) {
    int i = blockIdx.x;
    int t = threadIdx.x;
    int h = t / 8, k = t - h * 8;
    const float* R = rot + i * 9;
    const float* tr = trans + i * 3;
    float vy[3];
#pragma unroll
    for (int y = 0; y < 3; y++)
        vy[y] = g_respts[(size_t)i * 288 + h * 24 + k * 3 + y] - tr[y];
    float s = 1e-8f;
    float* fbase = g_feats + (size_t)i * DOUT;
#pragma unroll
    for (int x = 0; x < 3; x++) {
        float l = R[0 * 3 + x] * vy[0] + R[1 * 3 + x] * vy[1] + R[2 * 3 + x] * vy[2];
        fbase[1728 + h * 24 + k * 3 + x] = l;
        s += l * l;
    }
    fbase[2016 + h * 8 + k] = sqrtf(s);
}

// ================= pair MLP: register-chained, per-warp m16 x n128 =================
constexpr int W1P = 136, W2P = 136, EP = 56;
constexpr int OFF_W1H = 0;
constexpr int OFF_W1L = OFF_W1H + 48 * W1P * 2;
constexpr int OFF_W2H = OFF_W1L + 48 * W1P * 2;
constexpr int OFF_W2L = OFF_W2H + 128 * W2P * 2;
constexpr int OFF_E   = OFF_W2L + 128 * W2P * 2;
constexpr int EWBYTES = 16 * EP * 2;
constexpr int OFF_B1  = OFF_E + 8 * 2 * EWBYTES;
constexpr int OFF_B2  = OFF_B1 + 512;
constexpr int MLP_SMEM = OFF_B2 + 512;   // 125440

__global__ __launch_bounds__(256, 1) void k_pairmlp_mma(
    const float* __restrict__ Wp1, const float* __restrict__ bp1,
    const float* __restrict__ Wp2, const float* __restrict__ bp2,
    float* __restrict__ out)
{
    extern __shared__ char sm[];
    uint32_t sb = s2u(sm);
    int tid = threadIdx.x, lane = tid & 31, w = tid >> 5;

    for (int idx = tid; idx < 48 * 128; idx += 256) {
        int k = idx >> 7, n = idx & 127;
        float v = (k < 36) ? Wp1[k * 128 + n] : 0.f;
        split1(v, ((__nv_bfloat16*)(sm + OFF_W1H))[k * W1P + n],
                  ((__nv_bfloat16*)(sm + OFF_W1L))[k * W1P + n]);
    }
    for (int idx = tid; idx < 128 * 128; idx += 256) {
        int k = idx >> 7, n = idx & 127;
        split1(Wp2[idx], ((__nv_bfloat16*)(sm + OFF_W2H))[k * W2P + n],
                         ((__nv_bfloat16*)(sm + OFF_W2L))[k * W2P + n]);
    }
    if (tid < 128) {
        ((float*)(sm + OFF_B1))[tid] = bp1[tid];
        ((float*)(sm + OFF_B2))[tid] = bp2[tid];
    }
    {
        char* eh = sm + OFF_E + w * 2 * EWBYTES;
        char* el = eh + EWBYTES;
        for (int idx = lane; idx < 16 * 12; idx += 32) {
            int r = idx / 12, c = 36 + idx % 12;
            ((__nv_bfloat16*)eh)[r * EP + c] = __float2bfloat16_rn(0.f);
            ((__nv_bfloat16*)el)[r * EP + c] = __float2bfloat16_rn(0.f);
        }
    }
    __syncthreads();

    uint32_t ehBase = sb + OFF_E + w * 2 * EWBYTES;
    uint32_t elBase = ehBase + EWBYTES;
    uint32_t aAoff = (lane & 15) * (EP * 2) + (lane >> 4) * 16;
    int brow = (lane & 7) + ((lane >> 3) & 1) * 8, bc8 = (lane >> 4) * 8;
    uint32_t aBoff1 = brow * (W1P * 2) + bc8 * 2;
    uint32_t aBoff2 = brow * (W2P * 2) + bc8 * 2;
    const float* b1 = (const float*)(sm + OFF_B1);
    const float* b2 = (const float*)(sm + OFF_B2);

    for (int t = blockIdx.x; t < 4608; t += gridDim.x) {
        {
            int i = t / 6, j0 = (t % 6) * 128 + w * 16;
            const float* src = g_edge + ((size_t)i * 36) * NRES + j0;
            __nv_bfloat16* eh = (__nv_bfloat16*)(sm + OFF_E + w * 2 * EWBYTES);
            __nv_bfloat16* el = eh + 16 * EP;
            for (int idx = lane; idx < 576; idx += 32) {
                int c = idx >> 4, jj = idx & 15;
                float v = src[(size_t)c * NRES + jj];
                split1(v, eh[jj * EP + c], el[jj * EP + c]);
            }
            __syncwarp();
        }

        float acc[16][4];
#pragma unroll
        for (int n = 0; n < 16; n++) {
            float2 bb = *(const float2*)&b1[n * 8 + (lane & 3) * 2];
            acc[n][0] = bb.x; acc[n][1] = bb.y; acc[n][2] = bb.x; acc[n][3] = bb.y;
        }
#pragma unroll
        for (int ks = 0; ks < 3; ks++) {
            uint32_t ah[4], al[4];
            ldm4(ah, ehBase + aAoff + ks * 32);
            ldm4(al, elBase + aAoff + ks * 32);
#pragma unroll
            for (int n = 0; n < 8; n++) {
                uint32_t bh[4], bl[4];
                ldm4t(bh, sb + OFF_W1H + ks * 16 * (W1P * 2) + aBoff1 + n * 32);
                ldm4t(bl, sb + OFF_W1L + ks * 16 * (W1P * 2) + aBoff1 + n * 32);
                mma_bf16(acc[2 * n], ah, bh[0], bh[1]);
                mma_bf16(acc[2 * n], ah, bl[0], bl[1]);
                mma_bf16(acc[2 * n], al, bh[0], bh[1]);
                mma_bf16(acc[2 * n + 1], ah, bh[2], bh[3]);
                mma_bf16(acc[2 * n + 1], ah, bl[2], bl[3]);
                mma_bf16(acc[2 * n + 1], al, bh[2], bh[3]);
            }
        }

        uint32_t afH[8][4], afL[8][4];
#pragma unroll
        for (int kc = 0; kc < 8; kc++) {
            float g0 = gelu_exact(acc[2 * kc][0]),     g1 = gelu_exact(acc[2 * kc][1]);
            float g2 = gelu_exact(acc[2 * kc][2]),     g3 = gelu_exact(acc[2 * kc][3]);
            float g4 = gelu_exact(acc[2 * kc + 1][0]), g5 = gelu_exact(acc[2 * kc + 1][1]);
            float g6 = gelu_exact(acc[2 * kc + 1][2]), g7 = gelu_exact(acc[2 * kc + 1][3]);
            split2(g0, g1, afH[kc][0], afL[kc][0]);
            split2(g2, g3, afH[kc][1], afL[kc][1]);
            split2(g4, g5, afH[kc][2], afL[kc][2]);
            split2(g6, g7, afH[kc][3], afL[kc][3]);
        }

#pragma unroll
        for (int n = 0; n < 16; n++) {
            float2 bb = *(const float2*)&b2[n * 8 + (lane & 3) * 2];
            acc[n][0] = bb.x; acc[n][1] = bb.y; acc[n][2] = bb.x; acc[n][3] = bb.y;
        }
#pragma unroll
        for (int ks = 0; ks < 8; ks++) {
#pragma unroll
            for (int n = 0; n < 8; n++) {
                uint32_t bh[4], bl[4];
                ldm4t(bh, sb + OFF_W2H + ks * 16 * (W2P * 2) + aBoff2 + n * 32);
                ldm4t(bl, sb + OFF_W2L + ks * 16 * (W2P * 2) + aBoff2 + n * 32);
                mma_bf16(acc[2 * n], afH[ks], bh[0], bh[1]);
                mma_bf16(acc[2 * n], afH[ks], bl[0], bl[1]);
                mma_bf16(acc[2 * n], afL[ks], bh[0], bh[1]);
                mma_bf16(acc[2 * n + 1], afH[ks], bh[2], bh[3]);
                mma_bf16(acc[2 * n + 1], afH[ks], bl[2], bl[3]);
                mma_bf16(acc[2 * n + 1], afL[ks], bh[2], bh[3]);
            }
        }
        {
            float* dst = out + (size_t)t * 128 * 128;
            int rlo = w * 16 + (lane >> 2);
#pragma unroll
            for (int n = 0; n < 16; n++) {
                int c = n * 8 + (lane & 3) * 2;
                *(float2*)&dst[(size_t)rlo * 128 + c] = make_float2(acc[n][0], acc[n][1]);
                *(float2*)&dst[(size_t)(rlo + 8) * 128 + c] = make_float2(acc[n][2], acc[n][3]);
            }
        }
    }
}

// ---------------- host launcher ----------------
extern "C" void kernel_launch(void* const* d_in, const int* in_sizes, int n_in,
                              void* d_out, int out_size) {
    const float* scalar = (const float*)d_in[0];
    const float* pair   = (const float*)d_in[1];
    const float* rot    = (const float*)d_in[2];
    const float* trans  = (const float*)d_in[3];
    // d_in[4] = mask (all true; no-op)
    const float* Wqkv = (const float*)d_in[5];
    const float* Wpb  = (const float*)d_in[6];
    const float* pw   = (const float*)d_in[7];
    const float* Wout = (const float*)d_in[8];
    const float* bout = (const float*)d_in[9];
    const float* Wp1  = (const float*)d_in[10];
    const float* bp1  = (const float*)d_in[11];
    const float* Wp2  = (const float*)d_in[12];
    const float* bp2  = (const float*)d_in[13];
    float* out = (float*)d_out;

    cudaFuncSetAttribute(k_pairmlp_mma, cudaFuncAttributeMaxDynamicSharedMemorySize, MLP_SMEM);
    cudaFuncSetAttribute(k_fused, cudaFuncAttributeMaxDynamicSharedMemorySize, FUSED_SMEM);

    float* g_qkv_p;   cudaGetSymbolAddress((void**)&g_qkv_p, g_qkv);
    float* g_feats_p; cudaGetSymbolAddress((void**)&g_feats_p, g_feats);

    // (launch #4 is the one ncu profiles — keep k_fused there)
    gemm_mma3<<<dim3(DQKV / 128, NRES / 128), 256>>>(scalar, Wqkv, g_qkv_p, NRES, DQKV, DSC, nullptr);  // 1
    k_points<<<NRES, 192>>>(rot, trans);                                                                 // 2
    k_pack<<<NRES, 256>>>();                                                                             // 3
    k_fused<<<NRES, 512, FUSED_SMEM>>>(pair, Wpb, pw);                                                   // 4
    k_zero<<<(NRES * DSC + 255) / 256, 256>>>(out, bout);                                                // 5
    k_resv<<<dim3(NRES / 64, NH), 256>>>();                                                              // 6
    k_local<<<NRES, 96>>>(rot, trans);                                                                   // 7
    gemm_mma3_sk<<<dim3(DSC / 128, NRES / 128, 11), 256>>>(g_feats_p, Wout, out, NRES, DSC, DOUT, 192);  // 8
    k_pairmlp_mma<<<148, 256, MLP_SMEM>>>(Wp1, bp1, Wp2, bp2, out + NRES * DSC);                         // 9
}

// round 9
// speedup vs baseline: 1.5684x; 1.5684x over previous
#include <cuda_runtime.h>
#include <cuda_bf16.h>
#include <math.h>
#include <stdint.h>

// ---------------- problem constants ----------------
constexpr int NRES  = 768;
constexpr int NH    = 12;
constexpr long long NP = (long long)NRES * NRES;   // 589824
constexpr int DQKV  = 1152;
constexpr int DSC   = 384;
constexpr int DOUT  = 2112;
constexpr int QS_OFF = 0, KS_OFF = 192, VS_OFF = 384, QP_OFF = 576, KP_OFF = 720, VP_OFF = 864;
constexpr float SSC  = 0.14433756729740643f;
constexpr float PSC  = 0.13608276348795434f;
constexpr float PBSC = 0.5773502691896258f;

// ---------------- scratch ----------------
__device__ float g_qkv[NRES * DQKV];
__device__ float g_qp[NRES * 144];
__device__ float g_kp[NRES * 144];
__device__ float g_vp[NRES * 288];
__device__ float g_qpack[NRES * 336];      // [i][h*28+d]
__device__ float g_kpackT[336 * NRES];     // [h*28+d][j]
__device__ float g_edge[(size_t)NP * 36];  // [i][c][j] softmaxed; c<12 == attn head c
__device__ float g_feats[NRES * DOUT];
__device__ float g_respts[NRES * 288];

__device__ __forceinline__ float gelu_exact(float x) {
    return 0.5f * x * (1.0f + erff(x * 0.70710678118654752f));
}

// ---------------- mma helpers ----------------
__device__ __forceinline__ uint32_t s2u(const void* p) {
    uint32_t a;
    asm("{.reg .u64 t; cvta.to.shared.u64 t, %1; cvt.u32.u64 %0, t;}" : "=r"(a) : "l"(p));
    return a;
}
__device__ __forceinline__ void ldm4(uint32_t r[4], uint32_t a) {
    asm volatile("ldmatrix.sync.aligned.m8n8.x4.shared.b16 {%0,%1,%2,%3},[%4];"
                 : "=r"(r[0]), "=r"(r[1]), "=r"(r[2]), "=r"(r[3]) : "r"(a));
}
__device__ __forceinline__ void ldm4t(uint32_t r[4], uint32_t a) {
    asm volatile("ldmatrix.sync.aligned.m8n8.x4.trans.shared.b16 {%0,%1,%2,%3},[%4];"
                 : "=r"(r[0]), "=r"(r[1]), "=r"(r[2]), "=r"(r[3]) : "r"(a));
}
__device__ __forceinline__ void mma_bf16(float c[4], const uint32_t a[4], uint32_t b0, uint32_t b1) {
    asm volatile(
        "mma.sync.aligned.m16n8k16.row.col.f32.bf16.bf16.f32 "
        "{%0,%1,%2,%3},{%4,%5,%6,%7},{%8,%9},{%0,%1,%2,%3};"
        : "+f"(c[0]), "+f"(c[1]), "+f"(c[2]), "+f"(c[3])
        : "r"(a[0]), "r"(a[1]), "r"(a[2]), "r"(a[3]), "r"(b0), "r"(b1));
}
__device__ __forceinline__ void split1(float v, __nv_bfloat16& h, __nv_bfloat16& l) {
    h = __float2bfloat16_rn(v);
    l = __float2bfloat16_rn(v - __bfloat162float(h));
}
__device__ __forceinline__ void split2(float x, float y, uint32_t& hi, uint32_t& lo) {
    __nv_bfloat16 hx = __float2bfloat16_rn(x), hy = __float2bfloat16_rn(y);
    float rx = x - __bfloat162float(hx), ry = y - __bfloat162float(hy);
    __nv_bfloat162 th = __halves2bfloat162(hx, hy);
    __nv_bfloat162 tl = __floats2bfloat162_rn(rx, ry);
    hi = *reinterpret_cast<uint32_t*>(&th);
    lo = *reinterpret_cast<uint32_t*>(&tl);
}

// ---------------- generic 3-pass bf16 tensor-core GEMM (qkv) ----------------
constexpr int GAP = 24;
constexpr int GBP = 136;
__global__ __launch_bounds__(256) void gemm_mma3(
    const float* __restrict__ A, const float* __restrict__ B, float* __restrict__ C,
    int M, int N, int K, const float* __restrict__ bias)
{
    __shared__ __nv_bfloat16 Ah[128 * GAP], Al[128 * GAP];
    __shared__ __nv_bfloat16 Bh[16 * GBP],  Bl[16 * GBP];
    uint32_t sb_ah = s2u(Ah), sb_al = s2u(Al), sb_bh = s2u(Bh), sb_bl = s2u(Bl);
    int tid = threadIdx.x, lane = tid & 31, w = tid >> 5;
    int bm = blockIdx.y * 128, bn = blockIdx.x * 128;
    int r0 = w * 16;
    uint32_t aAoff = r0 * (GAP * 2) + (lane & 15) * (GAP * 2) + (lane >> 4) * 16;
    int brow = (lane & 7) + ((lane >> 3) & 1) * 8, bc8 = (lane >> 4) * 8;
    uint32_t aBoff = brow * (GBP * 2) + bc8 * 2;

    float acc[16][4] = {};
    for (int k0 = 0; k0 < K; k0 += 16) {
#pragma unroll
        for (int rep = 0; rep < 2; rep++) {
            int idx = tid + rep * 256;
            int row = idx >> 2, c4 = (idx & 3) * 4;
            float4 v = *(const float4*)&A[(size_t)(bm + row) * K + k0 + c4];
            split1(v.x, Ah[row * GAP + c4],     Al[row * GAP + c4]);
            split1(v.y, Ah[row * GAP + c4 + 1], Al[row * GAP + c4 + 1]);
            split1(v.z, Ah[row * GAP + c4 + 2], Al[row * GAP + c4 + 2]);
            split1(v.w, Ah[row * GAP + c4 + 3], Al[row * GAP + c4 + 3]);
            int browi = idx >> 5, bc4 = (idx & 31) * 4;
            float4 u = *(const float4*)&B[(size_t)(k0 + browi) * N + bn + bc4];
            split1(u.x, Bh[browi * GBP + bc4],     Bl[browi * GBP + bc4]);
            split1(u.y, Bh[browi * GBP + bc4 + 1], Bl[browi * GBP + bc4 + 1]);
            split1(u.z, Bh[browi * GBP + bc4 + 2], Bl[browi * GBP + bc4 + 2]);
            split1(u.w, Bh[browi * GBP + bc4 + 3], Bl[browi * GBP + bc4 + 3]);
        }
        __syncthreads();
        uint32_t ah[4], al[4];
        ldm4(ah, sb_ah + aAoff);
        ldm4(al, sb_al + aAoff);
#pragma unroll
        for (int n = 0; n < 8; n++) {
            uint32_t bh[4], bl[4];
            ldm4t(bh, sb_bh + aBoff + n * 32);
            ldm4t(bl, sb_bl + aBoff + n * 32);
            mma_bf16(acc[2 * n], ah, bh[0], bh[1]);
            mma_bf16(acc[2 * n], ah, bl[0], bl[1]);
            mma_bf16(acc[2 * n], al, bh[0], bh[1]);
            mma_bf16(acc[2 * n + 1], ah, bh[2], bh[3]);
            mma_bf16(acc[2 * n + 1], ah, bl[2], bl[3]);
            mma_bf16(acc[2 * n + 1], al, bh[2], bh[3]);
        }
        __syncthreads();
    }
    int rlo = bm + r0 + (lane >> 2);
#pragma unroll
    for (int n = 0; n < 16; n++) {
        int c = bn + n * 8 + (lane & 3) * 2;
        float b0 = bias ? bias[c] : 0.f, b1v = bias ? bias[c + 1] : 0.f;
        *(float2*)&C[(size_t)rlo * N + c] = make_float2(acc[n][0] + b0, acc[n][1] + b1v);
        *(float2*)&C[(size_t)(rlo + 8) * N + c] = make_float2(acc[n][2] + b0, acc[n][3] + b1v);
    }
}

// ---------------- split-K GEMM for scalar_out (atomicAdd epilogue) ----------------
__global__ __launch_bounds__(256) void gemm_mma3_sk(
    const float* __restrict__ A, const float* __restrict__ B, float* __restrict__ C,
    int M, int N, int K, int kchunk)
{
    __shared__ __nv_bfloat16 Ah[128 * GAP], Al[128 * GAP];
    __shared__ __nv_bfloat16 Bh[16 * GBP],  Bl[16 * GBP];
    uint32_t sb_ah = s2u(Ah), sb_al = s2u(Al), sb_bh = s2u(Bh), sb_bl = s2u(Bl);
    int tid = threadIdx.x, lane = tid & 31, w = tid >> 5;
    int bm = blockIdx.y * 128, bn = blockIdx.x * 128;
    int kbeg = blockIdx.z * kchunk, kend = kbeg + kchunk;
    int r0 = w * 16;
    uint32_t aAoff = r0 * (GAP * 2) + (lane & 15) * (GAP * 2) + (lane >> 4) * 16;
    int brow = (lane & 7) + ((lane >> 3) & 1) * 8, bc8 = (lane >> 4) * 8;
    uint32_t aBoff = brow * (GBP * 2) + bc8 * 2;

    float acc[16][4] = {};
    for (int k0 = kbeg; k0 < kend; k0 += 16) {
#pragma unroll
        for (int rep = 0; rep < 2; rep++) {
            int idx = tid + rep * 256;
            int row = idx >> 2, c4 = (idx & 3) * 4;
            float4 v = *(const float4*)&A[(size_t)(bm + row) * K + k0 + c4];
            split1(v.x, Ah[row * GAP + c4],     Al[row * GAP + c4]);
            split1(v.y, Ah[row * GAP + c4 + 1], Al[row * GAP + c4 + 1]);
            split1(v.z, Ah[row * GAP + c4 + 2], Al[row * GAP + c4 + 2]);
            split1(v.w, Ah[row * GAP + c4 + 3], Al[row * GAP + c4 + 3]);
            int browi = idx >> 5, bc4 = (idx & 31) * 4;
            float4 u = *(const float4*)&B[(size_t)(k0 + browi) * N + bn + bc4];
            split1(u.x, Bh[browi * GBP + bc4],     Bl[browi * GBP + bc4]);
            split1(u.y, Bh[browi * GBP + bc4 + 1], Bl[browi * GBP + bc4 + 1]);
            split1(u.z, Bh[browi * GBP + bc4 + 2], Bl[browi * GBP + bc4 + 2]);
            split1(u.w, Bh[browi * GBP + bc4 + 3], Bl[browi * GBP + bc4 + 3]);
        }
        __syncthreads();
        uint32_t ah[4], al[4];
        ldm4(ah, sb_ah + aAoff);
        ldm4(al, sb_al + aAoff);
#pragma unroll
        for (int n = 0; n < 8; n++) {
            uint32_t bh[4], bl[4];
            ldm4t(bh, sb_bh + aBoff + n * 32);
            ldm4t(bl, sb_bl + aBoff + n * 32);
            mma_bf16(acc[2 * n], ah, bh[0], bh[1]);
            mma_bf16(acc[2 * n], ah, bl[0], bl[1]);
            mma_bf16(acc[2 * n], al, bh[0], bh[1]);
            mma_bf16(acc[2 * n + 1], ah, bh[2], bh[3]);
            mma_bf16(acc[2 * n + 1], ah, bl[2], bl[3]);
            mma_bf16(acc[2 * n + 1], al, bh[2], bh[3]);
        }
        __syncthreads();
    }
    int rlo = bm + r0 + (lane >> 2);
#pragma unroll
    for (int n = 0; n < 16; n++) {
        int c = bn + n * 8 + (lane & 3) * 2;
        atomicAdd(&C[(size_t)rlo * N + c], acc[n][0]);
        atomicAdd(&C[(size_t)rlo * N + c + 1], acc[n][1]);
        atomicAdd(&C[(size_t)(rlo + 8) * N + c], acc[n][2]);
        atomicAdd(&C[(size_t)(rlo + 8) * N + c + 1], acc[n][3]);
    }
}

__global__ void k_zero(float* __restrict__ out, const float* __restrict__ bout) {
    int idx = blockIdx.x * 256 + threadIdx.x;
    if (idx < NRES * DSC) out[idx] = bout[idx % DSC];
}

// ---------------- points to global frame ----------------
__global__ void k_points(const float* __restrict__ rot, const float* __restrict__ trans) {
    int i = blockIdx.x;
    int t = threadIdx.x;
    const float* q = g_qkv + (size_t)i * DQKV;
    float p0, p1, p2;
    float* dst;
    if (t < 48) {
        int c0 = QP_OFF + t * 3;
        p0 = q[c0]; p1 = q[c0 + 1]; p2 = q[c0 + 2];
        dst = g_qp + i * 144 + t * 3;
    } else if (t < 96) {
        int u = t - 48, c0 = KP_OFF + u * 3;
        p0 = q[c0]; p1 = q[c0 + 1]; p2 = q[c0 + 2];
        dst = g_kp + i * 144 + u * 3;
    } else {
        int u = t - 96, c0 = VP_OFF + u * 3;
        p0 = q[c0]; p1 = q[c0 + 1]; p2 = q[c0 + 2];
        dst = g_vp + i * 288 + u * 3;
    }
    const float* R = rot + i * 9;
    const float* tr = trans + i * 3;
#pragma unroll
    for (int x = 0; x < 3; x++)
        dst[x] = R[x * 3 + 0] * p0 + R[x * 3 + 1] * p1 + R[x * 3 + 2] * p2 + tr[x];
}

// ---------------- pack q (row-major) and k (transposed) ----------------
__global__ void k_pack() {
    int i = blockIdx.x;
    for (int idx = threadIdx.x; idx < 336; idx += 256) {
        int h = idx / 28, d = idx - h * 28;
        float qv, kv;
        if (d < 16) {
            qv = g_qkv[(size_t)i * DQKV + QS_OFF + h * 16 + d];
            kv = g_qkv[(size_t)i * DQKV + KS_OFF + h * 16 + d];
        } else {
            qv = g_qp[i * 144 + h * 12 + (d - 16)];
            kv = g_kp[i * 144 + h * 12 + (d - 16)];
        }
        g_qpack[i * 336 + idx] = qv;
        g_kpackT[(size_t)idx * NRES + i] = kv;
    }
}

// ================= fused: pair-bias + qk logits + softmax + res_pair =================
// 512 threads (16 warps), ~217 KB smem, 1 CTA/SM
constexpr int LP = 776;
constexpr int F_LOG = 0;                       // [36][LP]
constexpr int F_W   = F_LOG + 36 * LP;         // 1536
constexpr int F_Q   = F_W + 1536;              // 352
constexpr int F_SPH = F_Q + 352;               // 16
constexpr int F_RED = F_SPH + 16;              // 16*1536 scratch (pair tile / pb partials / reduction)
constexpr int F_TOT = F_RED + 16 * 1536;
constexpr int FUSED_SMEM = F_TOT * 4;
// scratch sub-layout during pass A: tile 128x129 floats, then pb partials 4x128x13
constexpr int A_TILE = 0;            // within sRed
constexpr int A_PB   = 128 * 129;    // 16512
// pb partial pitch 13 -> conflict-free

__global__ __launch_bounds__(512, 1) void k_fused(
    const float* __restrict__ pair, const float* __restrict__ Wpb, const float* __restrict__ pw)
{
    extern __shared__ float sh[];
    float* sLog = sh + F_LOG;
    float* sW   = sh + F_W;
    float* sQ   = sh + F_Q;
    float* sSph = sh + F_SPH;
    float* sRed = sh + F_RED;
    int i = blockIdx.x, tid = threadIdx.x;
    int w = tid >> 5, lane = tid & 31;

    for (int idx = tid; idx < 1536; idx += 512) sW[idx] = Wpb[idx];
    for (int idx = tid; idx < 336; idx += 512) sQ[idx] = g_qpack[i * 336 + idx];
    if (tid < 12) sSph[tid] = log1pf(__expf(pw[tid]));
    __syncthreads();

    const float* prowbase = pair + (size_t)i * NRES * 128;

    // --- pass A1: pair-bias via smem-tiled GEMV; pb -> sLog channels 0..11 ---
    {
        float* sTile = sRed + A_TILE;   // [128][129]
        float* sPb   = sRed + A_PB;     // [4*128][13]
        int part = tid >> 7, jloc = tid & 127;   // 4 k-parts x 128 j
        int kbeg = part * 32;
        for (int jt = 0; jt < 6; jt++) {
            int j0 = jt * 128;
            // coalesced tile load: 4096 float4-equivalents? 128*128/4 = 4096 float4 loads
            for (int idx = tid; idx < 4096; idx += 512) {
                int row = idx >> 5, c4 = (idx & 31) * 4;
                float4 v = *(const float4*)(prowbase + (size_t)(j0 + row) * 128 + c4);
                float* d = sTile + row * 129 + c4;
                d[0] = v.x; d[1] = v.y; d[2] = v.z; d[3] = v.w;
            }
            __syncthreads();
            float pb[12] = {};
#pragma unroll 8
            for (int k = kbeg; k < kbeg + 32; k++) {
                float v = sTile[jloc * 129 + k];
                const float* wk = sW + k * 12;
#pragma unroll
                for (int h = 0; h < 12; h++) pb[h] += v * wk[h];
            }
            float* dstp = sPb + (part * 128 + jloc) * 13;
#pragma unroll
            for (int h = 0; h < 12; h++) dstp[h] = pb[h];
            __syncthreads();
            for (int idx = tid; idx < 1536; idx += 512) {
                int jl = idx / 12, h = idx - jl * 12;
                float s = sPb[(0 * 128 + jl) * 13 + h] + sPb[(1 * 128 + jl) * 13 + h]
                        + sPb[(2 * 128 + jl) * 13 + h] + sPb[(3 * 128 + jl) * 13 + h];
                sLog[h * LP + j0 + jl] = s;
            }
            __syncthreads();
        }
    }

    // --- pass A2: qk logits (coalesced via kpackT) + combine with pb ---
    for (int j = tid; j < NRES; j += 512) {
#pragma unroll
        for (int h = 0; h < 12; h++) {
            const float* qh = sQ + h * 28;
            const float* kb = g_kpackT + (size_t)(h * 28) * NRES + j;
            float sl = 0.f, pl = 0.f;
#pragma unroll
            for (int d = 0; d < 16; d++) sl += qh[d] * kb[(size_t)d * NRES];
#pragma unroll
            for (int d = 16; d < 28; d++) pl += qh[d] * kb[(size_t)d * NRES];
            float plv = pl * sSph[h];
            float pb = sLog[h * LP + j];
            sLog[h * LP + j]        = SSC * sl + PSC * plv + PBSC * pb;
            sLog[(12 + h) * LP + j] = plv;
            sLog[(24 + h) * LP + j] = sl;
        }
    }
    __syncthreads();

    // --- pass B: softmax per channel (warp per channel) ---
    {
        for (int c = w; c < 36; c += 16) {
            float* row = sLog + c * LP;
            float v[24];
            float m = -1e30f;
#pragma unroll
            for (int t = 0; t < 24; t++) { v[t] = row[lane + t * 32]; m = fmaxf(m, v[t]); }
#pragma unroll
            for (int s = 16; s > 0; s >>= 1) m = fmaxf(m, __shfl_xor_sync(0xffffffffu, m, s));
            float sum = 0.f;
#pragma unroll
            for (int t = 0; t < 24; t++) { v[t] = __expf(v[t] - m); sum += v[t]; }
#pragma unroll
            for (int s = 16; s > 0; s >>= 1) sum += __shfl_xor_sync(0xffffffffu, sum, s);
            float inv = 1.f / sum;
            float* dst = g_edge + ((size_t)i * 36 + c) * NRES;
#pragma unroll
            for (int t = 0; t < 24; t++) {
                float p = v[t] * inv;
                dst[lane + t * 32] = p;
                if (c < 12) row[lane + t * 32] = p;
            }
        }
    }
    __syncthreads();

    // --- pass D: res_pair; pair rows L2-hot from pass A1 ---
    {
        float acc[12][4] = {};
        for (int j = w; j < NRES; j += 16) {
            float4 v = *(const float4*)(prowbase + (size_t)j * 128 + lane * 4);
#pragma unroll
            for (int h = 0; h < 12; h++) {
                float a = sLog[h * LP + j];
                acc[h][0] += a * v.x; acc[h][1] += a * v.y;
                acc[h][2] += a * v.z; acc[h][3] += a * v.w;
            }
        }
        __syncthreads();
#pragma unroll
        for (int h = 0; h < 12; h++) {
            float* base = sRed + w * 1536 + h * 128 + lane * 4;
            base[0] = acc[h][0]; base[1] = acc[h][1]; base[2] = acc[h][2]; base[3] = acc[h][3];
        }
        __syncthreads();
        for (int idx = tid; idx < 1536; idx += 512) {
            float s = 0.f;
#pragma unroll
            for (int g = 0; g < 16; g++) s += sRed[g * 1536 + idx];
            int h = idx >> 7, d = idx & 127;
            g_feats[(size_t)i * DOUT + 192 + h * 128 + d] = s;
        }
    }
}

// ---------------- res_scalar + res_pts ----------------
__global__ __launch_bounds__(256) void k_resv() {
    int h = blockIdx.y;
    int i0 = blockIdx.x * 64;
    __shared__ float a[64][65];
    __shared__ float v[64][40];
    int tid = threadIdx.x;
    int io = tid & 63, og = tid >> 6;
    float acc[10] = {};
    for (int j0 = 0; j0 < NRES; j0 += 64) {
        for (int idx = tid; idx < 4096; idx += 256) {
            int ii = idx >> 6, jj = idx & 63;
            a[ii][jj] = g_edge[((size_t)(i0 + ii) * 36 + h) * NRES + j0 + jj];
        }
        for (int idx = tid; idx < 64 * 40; idx += 256) {
            int jj = idx / 40, o = idx - jj * 40;
            float val;
            if (o < 16) val = g_qkv[(size_t)(j0 + jj) * DQKV + VS_OFF + h * 16 + o];
            else        val = g_vp[(size_t)(j0 + jj) * 288 + h * 24 + (o - 16)];
            v[jj][o] = val;
        }
        __syncthreads();
#pragma unroll 4
        for (int jj = 0; jj < 64; jj++) {
            float av = a[io][jj];
#pragma unroll
            for (int q = 0; q < 10; q++) acc[q] += av * v[jj][og * 10 + q];
        }
        __syncthreads();
    }
#pragma unroll
    for (int q = 0; q < 10; q++) {
        int o = og * 10 + q;
        if (o < 16) g_feats[(size_t)(i0 + io) * DOUT + h * 16 + o] = acc[q];
        else        g_respts[(size_t)(i0 + io) * 288 + h * 24 + (o - 16)] = acc[q];
    }
}

// ---------------- inverse rigid + norms ----------------
__global__ void k_local(const float* __restrict__ rot, const float* __restrict__ trans) {
    int i = blockIdx.x;
    int t = threadIdx.x;
    int h = t / 8, k = t - h * 8;
    const float* R = rot + i * 9;
    const float* tr = trans + i * 3;
    float vy[3];
#pragma unroll
    for (int y = 0; y < 3; y++)
        vy[y] = g_respts[(size_t)i * 288 + h * 24 + k * 3 + y] - tr[y];
    float s = 1e-8f;
    float* fbase = g_feats + (size_t)i * DOUT;
#pragma unroll
    for (int x = 0; x < 3; x++) {
        float l = R[0 * 3 + x] * vy[0] + R[1 * 3 + x] * vy[1] + R[2 * 3 + x] * vy[2];
        fbase[1728 + h * 24 + k * 3 + x] = l;
        s += l * l;
    }
    fbase[2016 + h * 8 + k] = sqrtf(s);
}

// ================= pair MLP: register-chained, per-warp m16 x n128 =================
constexpr int W1P = 136, W2P = 136, EP = 56;
constexpr int OFF_W1H = 0;
constexpr int OFF_W1L = OFF_W1H + 48 * W1P * 2;
constexpr int OFF_W2H = OFF_W1L + 48 * W1P * 2;
constexpr int OFF_W2L = OFF_W2H + 128 * W2P * 2;
constexpr int OFF_E   = OFF_W2L + 128 * W2P * 2;
constexpr int EWBYTES = 16 * EP * 2;
constexpr int OFF_B1  = OFF_E + 8 * 2 * EWBYTES;
constexpr int OFF_B2  = OFF_B1 + 512;
constexpr int MLP_SMEM = OFF_B2 + 512;   // 125440

__global__ __launch_bounds__(256, 1) void k_pairmlp_mma(
    const float* __restrict__ Wp1, const float* __restrict__ bp1,
    const float* __restrict__ Wp2, const float* __restrict__ bp2,
    float* __restrict__ out)
{
    extern __shared__ char sm[];
    uint32_t sb = s2u(sm);
    int tid = threadIdx.x, lane = tid & 31, w = tid >> 5;

    for (int idx = tid; idx < 48 * 128; idx += 256) {
        int k = idx >> 7, n = idx & 127;
        float v = (k < 36) ? Wp1[k * 128 + n] : 0.f;
        split1(v, ((__nv_bfloat16*)(sm + OFF_W1H))[k * W1P + n],
                  ((__nv_bfloat16*)(sm + OFF_W1L))[k * W1P + n]);
    }
    for (int idx = tid; idx < 128 * 128; idx += 256) {
        int k = idx >> 7, n = idx & 127;
        split1(Wp2[idx], ((__nv_bfloat16*)(sm + OFF_W2H))[k * W2P + n],
                         ((__nv_bfloat16*)(sm + OFF_W2L))[k * W2P + n]);
    }
    if (tid < 128) {
        ((float*)(sm + OFF_B1))[tid] = bp1[tid];
        ((float*)(sm + OFF_B2))[tid] = bp2[tid];
    }
    {
        char* eh = sm + OFF_E + w * 2 * EWBYTES;
        char* el = eh + EWBYTES;
        for (int idx = lane; idx < 16 * 12; idx += 32) {
            int r = idx / 12, c = 36 + idx % 12;
            ((__nv_bfloat16*)eh)[r * EP + c] = __float2bfloat16_rn(0.f);
            ((__nv_bfloat16*)el)[r * EP + c] = __float2bfloat16_rn(0.f);
        }
    }
    __syncthreads();

    uint32_t ehBase = sb + OFF_E + w * 2 * EWBYTES;
    uint32_t elBase = ehBase + EWBYTES;
    uint32_t aAoff = (lane & 15) * (EP * 2) + (lane >> 4) * 16;
    int brow = (lane & 7) + ((lane >> 3) & 1) * 8, bc8 = (lane >> 4) * 8;
    uint32_t aBoff1 = brow * (W1P * 2) + bc8 * 2;
    uint32_t aBoff2 = brow * (W2P * 2) + bc8 * 2;
    const float* b1 = (const float*)(sm + OFF_B1);
    const float* b2 = (const float*)(sm + OFF_B2);

    for (int t = blockIdx.x; t < 4608; t += gridDim.x) {
        {
            int i = t / 6, j0 = (t % 6) * 128 + w * 16;
            const float* src = g_edge + ((size_t)i * 36) * NRES + j0;
            __nv_bfloat16* eh = (__nv_bfloat16*)(sm + OFF_E + w * 2 * EWBYTES);
            __nv_bfloat16* el = eh + 16 * EP;
            for (int idx = lane; idx < 576; idx += 32) {
                int c = idx >> 4, jj = idx & 15;
                float v = src[(size_t)c * NRES + jj];
                split1(v, eh[jj * EP + c], el[jj * EP + c]);
            }
            __syncwarp();
        }

        float acc[16][4];
#pragma unroll
        for (int n = 0; n < 16; n++) {
            float2 bb = *(const float2*)&b1[n * 8 + (lane & 3) * 2];
            acc[n][0] = bb.x; acc[n][1] = bb.y; acc[n][2] = bb.x; acc[n][3] = bb.y;
        }
#pragma unroll
        for (int ks = 0; ks < 3; ks++) {
            uint32_t ah[4], al[4];
            ldm4(ah, ehBase + aAoff + ks * 32);
            ldm4(al, elBase + aAoff + ks * 32);
#pragma unroll
            for (int n = 0; n < 8; n++) {
                uint32_t bh[4], bl[4];
                ldm4t(bh, sb + OFF_W1H + ks * 16 * (W1P * 2) + aBoff1 + n * 32);
                ldm4t(bl, sb + OFF_W1L + ks * 16 * (W1P * 2) + aBoff1 + n * 32);
                mma_bf16(acc[2 * n], ah, bh[0], bh[1]);
                mma_bf16(acc[2 * n], ah, bl[0], bl[1]);
                mma_bf16(acc[2 * n], al, bh[0], bh[1]);
                mma_bf16(acc[2 * n + 1], ah, bh[2], bh[3]);
                mma_bf16(acc[2 * n + 1], ah, bl[2], bl[3]);
                mma_bf16(acc[2 * n + 1], al, bh[2], bh[3]);
            }
        }

        uint32_t afH[8][4], afL[8][4];
#pragma unroll
        for (int kc = 0; kc < 8; kc++) {
            float g0 = gelu_exact(acc[2 * kc][0]),     g1 = gelu_exact(acc[2 * kc][1]);
            float g2 = gelu_exact(acc[2 * kc][2]),     g3 = gelu_exact(acc[2 * kc][3]);
            float g4 = gelu_exact(acc[2 * kc + 1][0]), g5 = gelu_exact(acc[2 * kc + 1][1]);
            float g6 = gelu_exact(acc[2 * kc + 1][2]), g7 = gelu_exact(acc[2 * kc + 1][3]);
            split2(g0, g1, afH[kc][0], afL[kc][0]);
            split2(g2, g3, afH[kc][1], afL[kc][1]);
            split2(g4, g5, afH[kc][2], afL[kc][2]);
            split2(g6, g7, afH[kc][3], afL[kc][3]);
        }

#pragma unroll
        for (int n = 0; n < 16; n++) {
            float2 bb = *(const float2*)&b2[n * 8 + (lane & 3) * 2];
            acc[n][0] = bb.x; acc[n][1] = bb.y; acc[n][2] = bb.x; acc[n][3] = bb.y;
        }
#pragma unroll
        for (int ks = 0; ks < 8; ks++) {
#pragma unroll
            for (int n = 0; n < 8; n++) {
                uint32_t bh[4], bl[4];
                ldm4t(bh, sb + OFF_W2H + ks * 16 * (W2P * 2) + aBoff2 + n * 32);
                ldm4t(bl, sb + OFF_W2L + ks * 16 * (W2P * 2) + aBoff2 + n * 32);
                mma_bf16(acc[2 * n], afH[ks], bh[0], bh[1]);
                mma_bf16(acc[2 * n], afH[ks], bl[0], bl[1]);
                mma_bf16(acc[2 * n], afL[ks], bh[0], bh[1]);
                mma_bf16(acc[2 * n + 1], afH[ks], bh[2], bh[3]);
                mma_bf16(acc[2 * n + 1], afH[ks], bl[2], bl[3]);
                mma_bf16(acc[2 * n + 1], afL[ks], bh[2], bh[3]);
            }
        }
        {
            float* dst = out + (size_t)t * 128 * 128;
            int rlo = w * 16 + (lane >> 2);
#pragma unroll
            for (int n = 0; n < 16; n++) {
                int c = n * 8 + (lane & 3) * 2;
                *(float2*)&dst[(size_t)rlo * 128 + c] = make_float2(acc[n][0], acc[n][1]);
                *(float2*)&dst[(size_t)(rlo + 8) * 128 + c] = make_float2(acc[n][2], acc[n][3]);
            }
        }
    }
}

// ---------------- host launcher ----------------
extern "C" void kernel_launch(void* const* d_in, const int* in_sizes, int n_in,
                              void* d_out, int out_size) {
    const float* scalar = (const float*)d_in[0];
    const float* pair   = (const float*)d_in[1];
    const float* rot    = (const float*)d_in[2];
    const float* trans  = (const float*)d_in[3];
    // d_in[4] = mask (all true; no-op)
    const float* Wqkv = (const float*)d_in[5];
    const float* Wpb  = (const float*)d_in[6];
    const float* pw   = (const float*)d_in[7];
    const float* Wout = (const float*)d_in[8];
    const float* bout = (const float*)d_in[9];
    const float* Wp1  = (const float*)d_in[10];
    const float* bp1  = (const float*)d_in[11];
    const float* Wp2  = (const float*)d_in[12];
    const float* bp2  = (const float*)d_in[13];
    float* out = (float*)d_out;

    cudaFuncSetAttribute(k_pairmlp_mma, cudaFuncAttributeMaxDynamicSharedMemorySize, MLP_SMEM);
    cudaFuncSetAttribute(k_fused, cudaFuncAttributeMaxDynamicSharedMemorySize, FUSED_SMEM);

    float* g_qkv_p;   cudaGetSymbolAddress((void**)&g_qkv_p, g_qkv);
    float* g_feats_p; cudaGetSymbolAddress((void**)&g_feats_p, g_feats);

    gemm_mma3<<<dim3(DQKV / 128, NRES / 128), 256>>>(scalar, Wqkv, g_qkv_p, NRES, DQKV, DSC, nullptr);  // 1
    k_points<<<NRES, 192>>>(rot, trans);                                                                 // 2
    k_pack<<<NRES, 256>>>();                                                                             // 3
    k_fused<<<NRES, 512, FUSED_SMEM>>>(pair, Wpb, pw);                                                   // 4 (profiled)
    k_zero<<<(NRES * DSC + 255) / 256, 256>>>(out, bout);                                                // 5
    k_resv<<<dim3(NRES / 64, NH), 256>>>();                                                              // 6
    k_local<<<NRES, 96>>>(rot, trans);                                                                   // 7
    gemm_mma3_sk<<<dim3(DSC / 128, NRES / 128, 11), 256>>>(g_feats_p, Wout, out, NRES, DSC, DOUT, 192);  // 8
    k_pairmlp_mma<<<148, 256, MLP_SMEM>>>(Wp1, bp1, Wp2, bp2, out + NRES * DSC);                         // 9
}

// round 10
// speedup vs baseline: 1.6796x; 1.0709x over previous
#include <cuda_runtime.h>
#include <cuda_bf16.h>
#include <math.h>
#include <stdint.h>

// ---------------- problem constants ----------------
constexpr int NRES  = 768;
constexpr int NH    = 12;
constexpr long long NP = (long long)NRES * NRES;   // 589824
constexpr int DQKV  = 1152;
constexpr int DSC   = 384;
constexpr int DOUT  = 2112;
constexpr int QS_OFF = 0, KS_OFF = 192, VS_OFF = 384, QP_OFF = 576, KP_OFF = 720, VP_OFF = 864;
constexpr float SSC  = 0.14433756729740643f;
constexpr float PSC  = 0.13608276348795434f;
constexpr float PBSC = 0.5773502691896258f;

// ---------------- scratch ----------------
__device__ float g_qkv[NRES * DQKV];
__device__ float g_qp[NRES * 144];
__device__ float g_kp[NRES * 144];
__device__ float g_vp[NRES * 288];
__device__ float g_qpack[NRES * 336];      // [i][h*28+d]
__device__ float g_kpackT[336 * NRES];     // [h*28+d][j]
__device__ float g_edge[(size_t)NP * 36];  // [i][c][j] softmaxed; c<12 == attn head c
__device__ float g_feats[NRES * DOUT];
__device__ float g_respts[NRES * 288];

__device__ __forceinline__ float gelu_exact(float x) {
    return 0.5f * x * (1.0f + erff(x * 0.70710678118654752f));
}

// ---------------- mma helpers ----------------
__device__ __forceinline__ uint32_t s2u(const void* p) {
    uint32_t a;
    asm("{.reg .u64 t; cvta.to.shared.u64 t, %1; cvt.u32.u64 %0, t;}" : "=r"(a) : "l"(p));
    return a;
}
__device__ __forceinline__ void ldm4(uint32_t r[4], uint32_t a) {
    asm volatile("ldmatrix.sync.aligned.m8n8.x4.shared.b16 {%0,%1,%2,%3},[%4];"
                 : "=r"(r[0]), "=r"(r[1]), "=r"(r[2]), "=r"(r[3]) : "r"(a));
}
__device__ __forceinline__ void ldm4t(uint32_t r[4], uint32_t a) {
    asm volatile("ldmatrix.sync.aligned.m8n8.x4.trans.shared.b16 {%0,%1,%2,%3},[%4];"
                 : "=r"(r[0]), "=r"(r[1]), "=r"(r[2]), "=r"(r[3]) : "r"(a));
}
__device__ __forceinline__ void mma_bf16(float c[4], const uint32_t a[4], uint32_t b0, uint32_t b1) {
    asm volatile(
        "mma.sync.aligned.m16n8k16.row.col.f32.bf16.bf16.f32 "
        "{%0,%1,%2,%3},{%4,%5,%6,%7},{%8,%9},{%0,%1,%2,%3};"
        : "+f"(c[0]), "+f"(c[1]), "+f"(c[2]), "+f"(c[3])
        : "r"(a[0]), "r"(a[1]), "r"(a[2]), "r"(a[3]), "r"(b0), "r"(b1));
}
__device__ __forceinline__ void split1(float v, __nv_bfloat16& h, __nv_bfloat16& l) {
    h = __float2bfloat16_rn(v);
    l = __float2bfloat16_rn(v - __bfloat162float(h));
}
__device__ __forceinline__ void split2(float x, float y, uint32_t& hi, uint32_t& lo) {
    __nv_bfloat16 hx = __float2bfloat16_rn(x), hy = __float2bfloat16_rn(y);
    float rx = x - __bfloat162float(hx), ry = y - __bfloat162float(hy);
    __nv_bfloat162 th = __halves2bfloat162(hx, hy);
    __nv_bfloat162 tl = __floats2bfloat162_rn(rx, ry);
    hi = *reinterpret_cast<uint32_t*>(&th);
    lo = *reinterpret_cast<uint32_t*>(&tl);
}

// ---------------- generic 3-pass bf16 tensor-core GEMM (qkv) ----------------
constexpr int GAP = 24;
constexpr int GBP = 136;
__global__ __launch_bounds__(256) void gemm_mma3(
    const float* __restrict__ A, const float* __restrict__ B, float* __restrict__ C,
    int M, int N, int K, const float* __restrict__ bias)
{
    __shared__ __nv_bfloat16 Ah[128 * GAP], Al[128 * GAP];
    __shared__ __nv_bfloat16 Bh[16 * GBP],  Bl[16 * GBP];
    uint32_t sb_ah = s2u(Ah), sb_al = s2u(Al), sb_bh = s2u(Bh), sb_bl = s2u(Bl);
    int tid = threadIdx.x, lane = tid & 31, w = tid >> 5;
    int bm = blockIdx.y * 128, bn = blockIdx.x * 128;
    int r0 = w * 16;
    uint32_t aAoff = r0 * (GAP * 2) + (lane & 15) * (GAP * 2) + (lane >> 4) * 16;
    int brow = (lane & 7) + ((lane >> 3) & 1) * 8, bc8 = (lane >> 4) * 8;
    uint32_t aBoff = brow * (GBP * 2) + bc8 * 2;

    float acc[16][4] = {};
    for (int k0 = 0; k0 < K; k0 += 16) {
#pragma unroll
        for (int rep = 0; rep < 2; rep++) {
            int idx = tid + rep * 256;
            int row = idx >> 2, c4 = (idx & 3) * 4;
            float4 v = *(const float4*)&A[(size_t)(bm + row) * K + k0 + c4];
            split1(v.x, Ah[row * GAP + c4],     Al[row * GAP + c4]);
            split1(v.y, Ah[row * GAP + c4 + 1], Al[row * GAP + c4 + 1]);
            split1(v.z, Ah[row * GAP + c4 + 2], Al[row * GAP + c4 + 2]);
            split1(v.w, Ah[row * GAP + c4 + 3], Al[row * GAP + c4 + 3]);
            int browi = idx >> 5, bc4 = (idx & 31) * 4;
            float4 u = *(const float4*)&B[(size_t)(k0 + browi) * N + bn + bc4];
            split1(u.x, Bh[browi * GBP + bc4],     Bl[browi * GBP + bc4]);
            split1(u.y, Bh[browi * GBP + bc4 + 1], Bl[browi * GBP + bc4 + 1]);
            split1(u.z, Bh[browi * GBP + bc4 + 2], Bl[browi * GBP + bc4 + 2]);
            split1(u.w, Bh[browi * GBP + bc4 + 3], Bl[browi * GBP + bc4 + 3]);
        }
        __syncthreads();
        uint32_t ah[4], al[4];
        ldm4(ah, sb_ah + aAoff);
        ldm4(al, sb_al + aAoff);
#pragma unroll
        for (int n = 0; n < 8; n++) {
            uint32_t bh[4], bl[4];
            ldm4t(bh, sb_bh + aBoff + n * 32);
            ldm4t(bl, sb_bl + aBoff + n * 32);
            mma_bf16(acc[2 * n], ah, bh[0], bh[1]);
            mma_bf16(acc[2 * n], ah, bl[0], bl[1]);
            mma_bf16(acc[2 * n], al, bh[0], bh[1]);
            mma_bf16(acc[2 * n + 1], ah, bh[2], bh[3]);
            mma_bf16(acc[2 * n + 1], ah, bl[2], bl[3]);
            mma_bf16(acc[2 * n + 1], al, bh[2], bh[3]);
        }
        __syncthreads();
    }
    int rlo = bm + r0 + (lane >> 2);
#pragma unroll
    for (int n = 0; n < 16; n++) {
        int c = bn + n * 8 + (lane & 3) * 2;
        float b0 = bias ? bias[c] : 0.f, b1v = bias ? bias[c + 1] : 0.f;
        *(float2*)&C[(size_t)rlo * N + c] = make_float2(acc[n][0] + b0, acc[n][1] + b1v);
        *(float2*)&C[(size_t)(rlo + 8) * N + c] = make_float2(acc[n][2] + b0, acc[n][3] + b1v);
    }
}

// ---------------- split-K GEMM for scalar_out (atomicAdd epilogue) ----------------
__global__ __launch_bounds__(256) void gemm_mma3_sk(
    const float* __restrict__ A, const float* __restrict__ B, float* __restrict__ C,
    int M, int N, int K, int kchunk)
{
    __shared__ __nv_bfloat16 Ah[128 * GAP], Al[128 * GAP];
    __shared__ __nv_bfloat16 Bh[16 * GBP],  Bl[16 * GBP];
    uint32_t sb_ah = s2u(Ah), sb_al = s2u(Al), sb_bh = s2u(Bh), sb_bl = s2u(Bl);
    int tid = threadIdx.x, lane = tid & 31, w = tid >> 5;
    int bm = blockIdx.y * 128, bn = blockIdx.x * 128;
    int kbeg = blockIdx.z * kchunk, kend = kbeg + kchunk;
    int r0 = w * 16;
    uint32_t aAoff = r0 * (GAP * 2) + (lane & 15) * (GAP * 2) + (lane >> 4) * 16;
    int brow = (lane & 7) + ((lane >> 3) & 1) * 8, bc8 = (lane >> 4) * 8;
    uint32_t aBoff = brow * (GBP * 2) + bc8 * 2;

    float acc[16][4] = {};
    for (int k0 = kbeg; k0 < kend; k0 += 16) {
#pragma unroll
        for (int rep = 0; rep < 2; rep++) {
            int idx = tid + rep * 256;
            int row = idx >> 2, c4 = (idx & 3) * 4;
            float4 v = *(const float4*)&A[(size_t)(bm + row) * K + k0 + c4];
            split1(v.x, Ah[row * GAP + c4],     Al[row * GAP + c4]);
            split1(v.y, Ah[row * GAP + c4 + 1], Al[row * GAP + c4 + 1]);
            split1(v.z, Ah[row * GAP + c4 + 2], Al[row * GAP + c4 + 2]);
            split1(v.w, Ah[row * GAP + c4 + 3], Al[row * GAP + c4 + 3]);
            int browi = idx >> 5, bc4 = (idx & 31) * 4;
            float4 u = *(const float4*)&B[(size_t)(k0 + browi) * N + bn + bc4];
            split1(u.x, Bh[browi * GBP + bc4],     Bl[browi * GBP + bc4]);
            split1(u.y, Bh[browi * GBP + bc4 + 1], Bl[browi * GBP + bc4 + 1]);
            split1(u.z, Bh[browi * GBP + bc4 + 2], Bl[browi * GBP + bc4 + 2]);
            split1(u.w, Bh[browi * GBP + bc4 + 3], Bl[browi * GBP + bc4 + 3]);
        }
        __syncthreads();
        uint32_t ah[4], al[4];
        ldm4(ah, sb_ah + aAoff);
        ldm4(al, sb_al + aAoff);
#pragma unroll
        for (int n = 0; n < 8; n++) {
            uint32_t bh[4], bl[4];
            ldm4t(bh, sb_bh + aBoff + n * 32);
            ldm4t(bl, sb_bl + aBoff + n * 32);
            mma_bf16(acc[2 * n], ah, bh[0], bh[1]);
            mma_bf16(acc[2 * n], ah, bl[0], bl[1]);
            mma_bf16(acc[2 * n], al, bh[0], bh[1]);
            mma_bf16(acc[2 * n + 1], ah, bh[2], bh[3]);
            mma_bf16(acc[2 * n + 1], ah, bl[2], bl[3]);
            mma_bf16(acc[2 * n + 1], al, bh[2], bh[3]);
        }
        __syncthreads();
    }
    int rlo = bm + r0 + (lane >> 2);
#pragma unroll
    for (int n = 0; n < 16; n++) {
        int c = bn + n * 8 + (lane & 3) * 2;
        atomicAdd(&C[(size_t)rlo * N + c], acc[n][0]);
        atomicAdd(&C[(size_t)rlo * N + c + 1], acc[n][1]);
        atomicAdd(&C[(size_t)(rlo + 8) * N + c], acc[n][2]);
        atomicAdd(&C[(size_t)(rlo + 8) * N + c + 1], acc[n][3]);
    }
}

__global__ void k_zero(float* __restrict__ out, const float* __restrict__ bout) {
    int idx = blockIdx.x * 256 + threadIdx.x;
    if (idx < NRES * DSC) out[idx] = bout[idx % DSC];
}

// ---------------- points to global frame ----------------
__global__ void k_points(const float* __restrict__ rot, const float* __restrict__ trans) {
    int i = blockIdx.x;
    int t = threadIdx.x;
    const float* q = g_qkv + (size_t)i * DQKV;
    float p0, p1, p2;
    float* dst;
    if (t < 48) {
        int c0 = QP_OFF + t * 3;
        p0 = q[c0]; p1 = q[c0 + 1]; p2 = q[c0 + 2];
        dst = g_qp + i * 144 + t * 3;
    } else if (t < 96) {
        int u = t - 48, c0 = KP_OFF + u * 3;
        p0 = q[c0]; p1 = q[c0 + 1]; p2 = q[c0 + 2];
        dst = g_kp + i * 144 + u * 3;
    } else {
        int u = t - 96, c0 = VP_OFF + u * 3;
        p0 = q[c0]; p1 = q[c0 + 1]; p2 = q[c0 + 2];
        dst = g_vp + i * 288 + u * 3;
    }
    const float* R = rot + i * 9;
    const float* tr = trans + i * 3;
#pragma unroll
    for (int x = 0; x < 3; x++)
        dst[x] = R[x * 3 + 0] * p0 + R[x * 3 + 1] * p1 + R[x * 3 + 2] * p2 + tr[x];
}

// ---------------- pack q (row-major) and k (transposed) ----------------
__global__ void k_pack() {
    int i = blockIdx.x;
    for (int idx = threadIdx.x; idx < 336; idx += 256) {
        int h = idx / 28, d = idx - h * 28;
        float qv, kv;
        if (d < 16) {
            qv = g_qkv[(size_t)i * DQKV + QS_OFF + h * 16 + d];
            kv = g_qkv[(size_t)i * DQKV + KS_OFF + h * 16 + d];
        } else {
            qv = g_qp[i * 144 + h * 12 + (d - 16)];
            kv = g_kp[i * 144 + h * 12 + (d - 16)];
        }
        g_qpack[i * 336 + idx] = qv;
        g_kpackT[(size_t)idx * NRES + i] = kv;
    }
}

// ================= fused: pair-bias + qk logits + softmax + res_pair (R9) =================
constexpr int LP = 776;
constexpr int F_LOG = 0;
constexpr int F_W   = F_LOG + 36 * LP;
constexpr int F_Q   = F_W + 1536;
constexpr int F_SPH = F_Q + 352;
constexpr int F_RED = F_SPH + 16;
constexpr int F_TOT = F_RED + 16 * 1536;
constexpr int FUSED_SMEM = F_TOT * 4;
constexpr int A_TILE = 0;
constexpr int A_PB   = 128 * 129;

__global__ __launch_bounds__(512, 1) void k_fused(
    const float* __restrict__ pair, const float* __restrict__ Wpb, const float* __restrict__ pw)
{
    extern __shared__ float sh[];
    float* sLog = sh + F_LOG;
    float* sW   = sh + F_W;
    float* sQ   = sh + F_Q;
    float* sSph = sh + F_SPH;
    float* sRed = sh + F_RED;
    int i = blockIdx.x, tid = threadIdx.x;
    int w = tid >> 5, lane = tid & 31;

    for (int idx = tid; idx < 1536; idx += 512) sW[idx] = Wpb[idx];
    for (int idx = tid; idx < 336; idx += 512) sQ[idx] = g_qpack[i * 336 + idx];
    if (tid < 12) sSph[tid] = log1pf(__expf(pw[tid]));
    __syncthreads();

    const float* prowbase = pair + (size_t)i * NRES * 128;

    // --- pass A1: pair-bias via smem-tiled GEMV ---
    {
        float* sTile = sRed + A_TILE;
        float* sPb   = sRed + A_PB;
        int part = tid >> 7, jloc = tid & 127;
        int kbeg = part * 32;
        for (int jt = 0; jt < 6; jt++) {
            int j0 = jt * 128;
            for (int idx = tid; idx < 4096; idx += 512) {
                int row = idx >> 5, c4 = (idx & 31) * 4;
                float4 v = *(const float4*)(prowbase + (size_t)(j0 + row) * 128 + c4);
                float* d = sTile + row * 129 + c4;
                d[0] = v.x; d[1] = v.y; d[2] = v.z; d[3] = v.w;
            }
            __syncthreads();
            float pb[12] = {};
#pragma unroll 8
            for (int k = kbeg; k < kbeg + 32; k++) {
                float v = sTile[jloc * 129 + k];
                const float* wk = sW + k * 12;
#pragma unroll
                for (int h = 0; h < 12; h++) pb[h] += v * wk[h];
            }
            float* dstp = sPb + (part * 128 + jloc) * 13;
#pragma unroll
            for (int h = 0; h < 12; h++) dstp[h] = pb[h];
            __syncthreads();
            for (int idx = tid; idx < 1536; idx += 512) {
                int jl = idx / 12, h = idx - jl * 12;
                float s = sPb[(0 * 128 + jl) * 13 + h] + sPb[(1 * 128 + jl) * 13 + h]
                        + sPb[(2 * 128 + jl) * 13 + h] + sPb[(3 * 128 + jl) * 13 + h];
                sLog[h * LP + j0 + jl] = s;
            }
            __syncthreads();
        }
    }

    // --- pass A2: qk logits + combine ---
    for (int j = tid; j < NRES; j += 512) {
#pragma unroll
        for (int h = 0; h < 12; h++) {
            const float* qh = sQ + h * 28;
            const float* kb = g_kpackT + (size_t)(h * 28) * NRES + j;
            float sl = 0.f, pl = 0.f;
#pragma unroll
            for (int d = 0; d < 16; d++) sl += qh[d] * kb[(size_t)d * NRES];
#pragma unroll
            for (int d = 16; d < 28; d++) pl += qh[d] * kb[(size_t)d * NRES];
            float plv = pl * sSph[h];
            float pb = sLog[h * LP + j];
            sLog[h * LP + j]        = SSC * sl + PSC * plv + PBSC * pb;
            sLog[(12 + h) * LP + j] = plv;
            sLog[(24 + h) * LP + j] = sl;
        }
    }
    __syncthreads();

    // --- pass B: softmax ---
    {
        for (int c = w; c < 36; c += 16) {
            float* row = sLog + c * LP;
            float v[24];
            float m = -1e30f;
#pragma unroll
            for (int t = 0; t < 24; t++) { v[t] = row[lane + t * 32]; m = fmaxf(m, v[t]); }
#pragma unroll
            for (int s = 16; s > 0; s >>= 1) m = fmaxf(m, __shfl_xor_sync(0xffffffffu, m, s));
            float sum = 0.f;
#pragma unroll
            for (int t = 0; t < 24; t++) { v[t] = __expf(v[t] - m); sum += v[t]; }
#pragma unroll
            for (int s = 16; s > 0; s >>= 1) sum += __shfl_xor_sync(0xffffffffu, sum, s);
            float inv = 1.f / sum;
            float* dst = g_edge + ((size_t)i * 36 + c) * NRES;
#pragma unroll
            for (int t = 0; t < 24; t++) {
                float p = v[t] * inv;
                dst[lane + t * 32] = p;
                if (c < 12) row[lane + t * 32] = p;
            }
        }
    }
    __syncthreads();

    // --- pass D: res_pair ---
    {
        float acc[12][4] = {};
        for (int j = w; j < NRES; j += 16) {
            float4 v = *(const float4*)(prowbase + (size_t)j * 128 + lane * 4);
#pragma unroll
            for (int h = 0; h < 12; h++) {
                float a = sLog[h * LP + j];
                acc[h][0] += a * v.x; acc[h][1] += a * v.y;
                acc[h][2] += a * v.z; acc[h][3] += a * v.w;
            }
        }
        __syncthreads();
#pragma unroll
        for (int h = 0; h < 12; h++) {
            float* base = sRed + w * 1536 + h * 128 + lane * 4;
            base[0] = acc[h][0]; base[1] = acc[h][1]; base[2] = acc[h][2]; base[3] = acc[h][3];
        }
        __syncthreads();
        for (int idx = tid; idx < 1536; idx += 512) {
            float s = 0.f;
#pragma unroll
            for (int g = 0; g < 16; g++) s += sRed[g * 1536 + idx];
            int h = idx >> 7, d = idx & 127;
            g_feats[(size_t)i * DOUT + 192 + h * 128 + d] = s;
        }
    }
}

// ---------------- res_scalar + res_pts ----------------
__global__ __launch_bounds__(256) void k_resv() {
    int h = blockIdx.y;
    int i0 = blockIdx.x * 64;
    __shared__ float a[64][65];
    __shared__ float v[64][40];
    int tid = threadIdx.x;
    int io = tid & 63, og = tid >> 6;
    float acc[10] = {};
    for (int j0 = 0; j0 < NRES; j0 += 64) {
        for (int idx = tid; idx < 4096; idx += 256) {
            int ii = idx >> 6, jj = idx & 63;
            a[ii][jj] = g_edge[((size_t)(i0 + ii) * 36 + h) * NRES + j0 + jj];
        }
        for (int idx = tid; idx < 64 * 40; idx += 256) {
            int jj = idx / 40, o = idx - jj * 40;
            float val;
            if (o < 16) val = g_qkv[(size_t)(j0 + jj) * DQKV + VS_OFF + h * 16 + o];
            else        val = g_vp[(size_t)(j0 + jj) * 288 + h * 24 + (o - 16)];
            v[jj][o] = val;
        }
        __syncthreads();
#pragma unroll 4
        for (int jj = 0; jj < 64; jj++) {
            float av = a[io][jj];
#pragma unroll
            for (int q = 0; q < 10; q++) acc[q] += av * v[jj][og * 10 + q];
        }
        __syncthreads();
    }
#pragma unroll
    for (int q = 0; q < 10; q++) {
        int o = og * 10 + q;
        if (o < 16) g_feats[(size_t)(i0 + io) * DOUT + h * 16 + o] = acc[q];
        else        g_respts[(size_t)(i0 + io) * 288 + h * 24 + (o - 16)] = acc[q];
    }
}

// ---------------- inverse rigid + norms ----------------
__global__ void k_local(const float* __restrict__ rot, const float* __restrict__ trans) {
    int i = blockIdx.x;
    int t = threadIdx.x;
    int h = t / 8, k = t - h * 8;
    const float* R = rot + i * 9;
    const float* tr = trans + i * 3;
    float vy[3];
#pragma unroll
    for (int y = 0; y < 3; y++)
        vy[y] = g_respts[(size_t)i * 288 + h * 24 + k * 3 + y] - tr[y];
    float s = 1e-8f;
    float* fbase = g_feats + (size_t)i * DOUT;
#pragma unroll
    for (int x = 0; x < 3; x++) {
        float l = R[0 * 3 + x] * vy[0] + R[1 * 3 + x] * vy[1] + R[2 * 3 + x] * vy[2];
        fbase[1728 + h * 24 + k * 3 + x] = l;
        s += l * l;
    }
    fbase[2016 + h * 8 + k] = sqrtf(s);
}

// ================= pair MLP: 16 warps = 2 teams x 2 tiles, n-halved register budget =================
constexpr int W1P = 136, W2P = 136, EP = 56;
constexpr int OFF_W1H = 0;
constexpr int OFF_W1L = OFF_W1H + 48 * W1P * 2;
constexpr int OFF_W2H = OFF_W1L + 48 * W1P * 2;
constexpr int OFF_W2L = OFF_W2H + 128 * W2P * 2;
constexpr int OFF_E   = OFF_W2L + 128 * W2P * 2;
constexpr int EWBYTES = 16 * EP * 2;
constexpr int OFF_B1  = OFF_E + 16 * 2 * EWBYTES;   // 16 warp slots
constexpr int OFF_B2  = OFF_B1 + 512;
constexpr int MLP_SMEM = OFF_B2 + 512;   // 154112

__global__ __launch_bounds__(512, 1) void k_pairmlp_mma(
    const float* __restrict__ Wp1, const float* __restrict__ bp1,
    const float* __restrict__ Wp2, const float* __restrict__ bp2,
    float* __restrict__ out)
{
    extern __shared__ char sm[];
    uint32_t sb = s2u(sm);
    int tid = threadIdx.x, lane = tid & 31, w = tid >> 5;
    int team = w >> 3, wq = w & 7;

    for (int idx = tid; idx < 48 * 128; idx += 512) {
        int k = idx >> 7, n = idx & 127;
        float v = (k < 36) ? Wp1[k * 128 + n] : 0.f;
        split1(v, ((__nv_bfloat16*)(sm + OFF_W1H))[k * W1P + n],
                  ((__nv_bfloat16*)(sm + OFF_W1L))[k * W1P + n]);
    }
    for (int idx = tid; idx < 128 * 128; idx += 512) {
        int k = idx >> 7, n = idx & 127;
        split1(Wp2[idx], ((__nv_bfloat16*)(sm + OFF_W2H))[k * W2P + n],
                         ((__nv_bfloat16*)(sm + OFF_W2L))[k * W2P + n]);
    }
    if (tid < 128) {
        ((float*)(sm + OFF_B1))[tid] = bp1[tid];
        ((float*)(sm + OFF_B2))[tid] = bp2[tid];
    }
    {
        char* eh = sm + OFF_E + w * 2 * EWBYTES;
        char* el = eh + EWBYTES;
        for (int idx = lane; idx < 16 * 12; idx += 32) {
            int r = idx / 12, c = 36 + idx % 12;
            ((__nv_bfloat16*)eh)[r * EP + c] = __float2bfloat16_rn(0.f);
            ((__nv_bfloat16*)el)[r * EP + c] = __float2bfloat16_rn(0.f);
        }
    }
    __syncthreads();   // after this: no block syncs (per-warp independence)

    uint32_t ehBase = sb + OFF_E + w * 2 * EWBYTES;
    uint32_t elBase = ehBase + EWBYTES;
    uint32_t aAoff = (lane & 15) * (EP * 2) + (lane >> 4) * 16;
    int brow = (lane & 7) + ((lane >> 3) & 1) * 8, bc8 = (lane >> 4) * 8;
    uint32_t aBoff1 = brow * (W1P * 2) + bc8 * 2;
    uint32_t aBoff2 = brow * (W2P * 2) + bc8 * 2;
    const float* b1 = (const float*)(sm + OFF_B1);
    const float* b2 = (const float*)(sm + OFF_B2);

    for (int t2 = blockIdx.x; t2 < 2304; t2 += gridDim.x) {
        int t = t2 * 2 + team;
        // stage this warp's 16 E rows
        {
            int i = t / 6, j0 = (t % 6) * 128 + wq * 16;
            const float* src = g_edge + ((size_t)i * 36) * NRES + j0;
            __nv_bfloat16* eh = (__nv_bfloat16*)(sm + OFF_E + w * 2 * EWBYTES);
            __nv_bfloat16* el = eh + 16 * EP;
            for (int idx = lane; idx < 576; idx += 32) {
                int c = idx >> 4, jj = idx & 15;
                float v = src[(size_t)c * NRES + jj];
                split1(v, eh[jj * EP + c], el[jj * EP + c]);
            }
            __syncwarp();
        }

        // ---- layer 1 in two n-halves; af fragments built across halves ----
        uint32_t afH[8][4], afL[8][4];
#pragma unroll
        for (int half = 0; half < 2; half++) {
            float acc[8][4];
#pragma unroll
            for (int n = 0; n < 8; n++) {
                float2 bb = *(const float2*)&b1[half * 64 + n * 8 + (lane & 3) * 2];
                acc[n][0] = bb.x; acc[n][1] = bb.y; acc[n][2] = bb.x; acc[n][3] = bb.y;
            }
#pragma unroll
            for (int ks = 0; ks < 3; ks++) {
                uint32_t ah[4], al[4];
                ldm4(ah, ehBase + aAoff + ks * 32);
                ldm4(al, elBase + aAoff + ks * 32);
#pragma unroll
                for (int n = 0; n < 4; n++) {
                    uint32_t bh[4], bl[4];
                    uint32_t boff = aBoff1 + half * 128 + n * 32;
                    ldm4t(bh, sb + OFF_W1H + ks * 16 * (W1P * 2) + boff);
                    ldm4t(bl, sb + OFF_W1L + ks * 16 * (W1P * 2) + boff);
                    mma_bf16(acc[2 * n], ah, bh[0], bh[1]);
                    mma_bf16(acc[2 * n], ah, bl[0], bl[1]);
                    mma_bf16(acc[2 * n], al, bh[0], bh[1]);
                    mma_bf16(acc[2 * n + 1], ah, bh[2], bh[3]);
                    mma_bf16(acc[2 * n + 1], ah, bl[2], bl[3]);
                    mma_bf16(acc[2 * n + 1], al, bh[2], bh[3]);
                }
            }
#pragma unroll
            for (int n = 0; n < 4; n++) {
                int kc = half * 4 + n;
                float g0 = gelu_exact(acc[2 * n][0]),     g1 = gelu_exact(acc[2 * n][1]);
                float g2 = gelu_exact(acc[2 * n][2]),     g3 = gelu_exact(acc[2 * n][3]);
                float g4 = gelu_exact(acc[2 * n + 1][0]), g5 = gelu_exact(acc[2 * n + 1][1]);
                float g6 = gelu_exact(acc[2 * n + 1][2]), g7 = gelu_exact(acc[2 * n + 1][3]);
                split2(g0, g1, afH[kc][0], afL[kc][0]);
                split2(g2, g3, afH[kc][1], afL[kc][1]);
                split2(g4, g5, afH[kc][2], afL[kc][2]);
                split2(g6, g7, afH[kc][3], afL[kc][3]);
            }
        }

        // ---- layer 2 in two n-halves ----
        float* dst = out + (size_t)t * 128 * 128;
        int rlo = wq * 16 + (lane >> 2);
#pragma unroll
        for (int half = 0; half < 2; half++) {
            float acc[8][4];
#pragma unroll
            for (int n = 0; n < 8; n++) {
                float2 bb = *(const float2*)&b2[half * 64 + n * 8 + (lane & 3) * 2];
                acc[n][0] = bb.x; acc[n][1] = bb.y; acc[n][2] = bb.x; acc[n][3] = bb.y;
            }
#pragma unroll
            for (int ks = 0; ks < 8; ks++) {
#pragma unroll
                for (int n = 0; n < 4; n++) {
                    uint32_t bh[4], bl[4];
                    uint32_t boff = aBoff2 + half * 128 + n * 32;
                    ldm4t(bh, sb + OFF_W2H + ks * 16 * (W2P * 2) + boff);
                    ldm4t(bl, sb + OFF_W2L + ks * 16 * (W2P * 2) + boff);
                    mma_bf16(acc[2 * n], afH[ks], bh[0], bh[1]);
                    mma_bf16(acc[2 * n], afH[ks], bl[0], bl[1]);
                    mma_bf16(acc[2 * n], afL[ks], bh[0], bh[1]);
                    mma_bf16(acc[2 * n + 1], afH[ks], bh[2], bh[3]);
                    mma_bf16(acc[2 * n + 1], afH[ks], bl[2], bl[3]);
                    mma_bf16(acc[2 * n + 1], afL[ks], bh[2], bh[3]);
                }
            }
#pragma unroll
            for (int n = 0; n < 8; n++) {
                int c = half * 64 + n * 8 + (lane & 3) * 2;
                *(float2*)&dst[(size_t)rlo * 128 + c] = make_float2(acc[n][0], acc[n][1]);
                *(float2*)&dst[(size_t)(rlo + 8) * 128 + c] = make_float2(acc[n][2], acc[n][3]);
            }
        }
    }
}

// ---------------- host launcher ----------------
extern "C" void kernel_launch(void* const* d_in, const int* in_sizes, int n_in,
                              void* d_out, int out_size) {
    const float* scalar = (const float*)d_in[0];
    const float* pair   = (const float*)d_in[1];
    const float* rot    = (const float*)d_in[2];
    const float* trans  = (const float*)d_in[3];
    // d_in[4] = mask (all true; no-op)
    const float* Wqkv = (const float*)d_in[5];
    const float* Wpb  = (const float*)d_in[6];
    const float* pw   = (const float*)d_in[7];
    const float* Wout = (const float*)d_in[8];
    const float* bout = (const float*)d_in[9];
    const float* Wp1  = (const float*)d_in[10];
    const float* bp1  = (const float*)d_in[11];
    const float* Wp2  = (const float*)d_in[12];
    const float* bp2  = (const float*)d_in[13];
    float* out = (float*)d_out;

    cudaFuncSetAttribute(k_pairmlp_mma, cudaFuncAttributeMaxDynamicSharedMemorySize, MLP_SMEM);
    cudaFuncSetAttribute(k_fused, cudaFuncAttributeMaxDynamicSharedMemorySize, FUSED_SMEM);

    float* g_qkv_p;   cudaGetSymbolAddress((void**)&g_qkv_p, g_qkv);
    float* g_feats_p; cudaGetSymbolAddress((void**)&g_feats_p, g_feats);

    gemm_mma3<<<dim3(DQKV / 128, NRES / 128), 256>>>(scalar, Wqkv, g_qkv_p, NRES, DQKV, DSC, nullptr);  // 1
    k_points<<<NRES, 192>>>(rot, trans);                                                                 // 2
    k_pack<<<NRES, 256>>>();                                                                             // 3
    k_fused<<<NRES, 512, FUSED_SMEM>>>(pair, Wpb, pw);                                                   // 4
    k_zero<<<(NRES * DSC + 255) / 256, 256>>>(out, bout);                                                // 5
    k_resv<<<dim3(NRES / 64, NH), 256>>>();                                                              // 6
    k_local<<<NRES, 96>>>(rot, trans);                                                                   // 7
    gemm_mma3_sk<<<dim3(DSC / 128, NRES / 128, 11), 256>>>(g_feats_p, Wout, out, NRES, DSC, DOUT, 192);  // 8
    k_pairmlp_mma<<<148, 512, MLP_SMEM>>>(Wp1, bp1, Wp2, bp2, out + NRES * DSC);                         // 9
}